// round 10
// baseline (speedup 1.0000x reference)
#include <cuda_runtime.h>
#include <stdint.h>

#define N_NODES 10242
#define NNZ_MAX 71694
#define BT      32          // B*T
#define C_IN    16
#define F       512         // C_IN * BT
#define KS      20
#define COUT    32
#define CK      (C_IN * KS)
#define SORT_BLOCKS 41      // 41*256 >= 10242
#define XP_BLOCKS   ((N_NODES + 7) / 8)
#define WARP_BLOCKS ((N_NODES * 32 + 255) / 256)
#define PROJ_BLOCKS ((N_NODES * 2 * 32 + 255) / 256)   // 2 warps per node

typedef unsigned long long ull;

// ---------------- device scratch (no runtime allocation allowed) ----------------
__device__ float g_buf[(size_t)4 * N_NODES * F];   // rolling 4-slice window (~84MB, L2-resident)
__device__ int   g_rowptr[N_NODES + 1];
__device__ int   g_cursor[N_NODES];
__device__ int   g_colidx[NNZ_MAX];
__device__ float g_vals[NNZ_MAX];
__device__ float g_Wd[KS * C_IN * COUT * 2];       // pre-duplicated: [k][c][cout*2] = {w,w} (80KB)

// ---------------- kernel A: count+scan+W-reshape (single block) ----------------
__global__ void __launch_bounds__(1024) prep_kernel(const int* __restrict__ erow,
                                                    const float* __restrict__ W,
                                                    int nnz) {
    __shared__ int scnt[N_NODES];
    __shared__ int ssum[1024];
    int t = threadIdx.x;

    for (int i = t; i < N_NODES; i += 1024) scnt[i] = 0;
    __syncthreads();
    for (int e = t; e < nnz; e += 1024) atomicAdd(&scnt[erow[e]], 1);
    __syncthreads();

    const int CH = 11;                 // 1024*11 >= 10242
    int base = t * CH;
    int s = 0;
#pragma unroll
    for (int i = 0; i < CH; ++i) {
        int idx = base + i;
        if (idx < N_NODES) s += scnt[idx];
    }
    ssum[t] = s;
    __syncthreads();
    for (int off = 1; off < 1024; off <<= 1) {
        int v = (t >= off) ? ssum[t - off] : 0;
        __syncthreads();
        ssum[t] += v;
        __syncthreads();
    }
    int run = ssum[t] - s;
#pragma unroll
    for (int i = 0; i < CH; ++i) {
        int idx = base + i;
        if (idx < N_NODES) {
            g_rowptr[idx] = run;
            g_cursor[idx] = run;
            run += scnt[idx];
        }
    }
    if (t == 0) g_rowptr[N_NODES] = nnz;

    // W pre-duplicated: g_Wd[k*1024 + c*64 + cout*2 (+1)] = W[cout*CK + c*KS + k]
    for (int i = t; i < KS * C_IN * COUT; i += 1024) {
        int k = i >> 9;
        int r = i & 511;
        int c = r >> 5;
        int cout = r & 31;
        float v = W[cout * CK + c * KS + k];
        g_Wd[k * 1024 + c * 64 + cout * 2]     = v;
        g_Wd[k * 1024 + c * 64 + cout * 2 + 1] = v;
    }
}

// ---------------- kernel B: scatter ----------------
__global__ void csr_scatter_kernel(const int* __restrict__ erow,
                                   const int* __restrict__ ecol,
                                   const float* __restrict__ eval, int nnz) {
    int e = blockIdx.x * blockDim.x + threadIdx.x;
    if (e < nnz) {
        int r = erow[e];
        int p = atomicAdd(&g_cursor[r], 1);
        g_colidx[p] = ecol[e];
        g_vals[p]   = eval[e];
    }
}

// ---------------- kernel C: per-row sort + transpose slice 0 (split grid) ----------------
__global__ void __launch_bounds__(256) sort_xpose_kernel(const float* __restrict__ x) {
    if (blockIdx.x < SORT_BLOCKS) {
        // canonical per-row order (col asc, then val asc) -> deterministic fp sums
        int r = blockIdx.x * 256 + threadIdx.x;
        if (r >= N_NODES) return;
        int s = g_rowptr[r], e = g_rowptr[r + 1];
        for (int i = s + 1; i < e; ++i) {
            int   kc = g_colidx[i];
            float kv = g_vals[i];
            int j = i - 1;
            while (j >= s && (g_colidx[j] > kc || (g_colidx[j] == kc && g_vals[j] > kv))) {
                g_colidx[j + 1] = g_colidx[j];
                g_vals[j + 1]   = g_vals[j];
                --j;
            }
            g_colidx[j + 1] = kc;
            g_vals[j + 1]   = kv;
        }
        return;
    }
    // transpose: x[bt=lane, n, c] -> g_buf[slot0][n, c*32+lane]
    int tid  = threadIdx.x;
    int wid  = tid >> 5;
    int lane = tid & 31;
    int n = (blockIdx.x - SORT_BLOCKS) * 8 + wid;
    if (n >= N_NODES) return;

    const float* xp = x + ((size_t)lane * N_NODES + n) * C_IN;
    float4 v0 = __ldg((const float4*)xp);
    float4 v1 = __ldg((const float4*)(xp + 4));
    float4 v2 = __ldg((const float4*)(xp + 8));
    float4 v3 = __ldg((const float4*)(xp + 12));
    float vals[16] = {v0.x, v0.y, v0.z, v0.w, v1.x, v1.y, v1.z, v1.w,
                      v2.x, v2.y, v2.z, v2.w, v3.x, v3.y, v3.z, v3.w};
    float* dst = g_buf + (size_t)n * F;
#pragma unroll
    for (int c = 0; c < C_IN; ++c) dst[c * BT + lane] = vals[c];
}

// ---------------- SpMM step (R2/R7-validated; rolling buffer mod 4) ----------------
#define FMA4(A, V, U) do { \
    A.x = fmaf(V, U.x, A.x); A.y = fmaf(V, U.y, A.y); \
    A.z = fmaf(V, U.z, A.z); A.w = fmaf(V, U.w, A.w); } while (0)

__global__ void __launch_bounds__(256) spmm_kernel(int kc, int kp, int ko, int first) {
    int gw   = (blockIdx.x * 256 + threadIdx.x) >> 5;   // node = global warp id
    int lane = threadIdx.x & 31;
    if (gw >= N_NODES) return;

    const float4* __restrict__ cur = (const float4*)(g_buf + (size_t)kc * N_NODES * F);
    int s = g_rowptr[gw], e = g_rowptr[gw + 1];

    float4 a0 = make_float4(0.f, 0.f, 0.f, 0.f), a1 = a0, a2 = a0, a3 = a0;

    int i = s;
    for (; i + 2 <= e; i += 2) {
        int   c0 = __ldg(&g_colidx[i]);
        int   c1 = __ldg(&g_colidx[i + 1]);
        float v0 = __ldg(&g_vals[i]);
        float v1 = __ldg(&g_vals[i + 1]);
        const float4* p0 = cur + (size_t)c0 * 128 + lane;
        const float4* p1 = cur + (size_t)c1 * 128 + lane;
        float4 u0 = __ldg(p0),      u1 = __ldg(p0 + 32),
               u2 = __ldg(p0 + 64), u3 = __ldg(p0 + 96);
        float4 w0 = __ldg(p1),      w1 = __ldg(p1 + 32),
               w2 = __ldg(p1 + 64), w3 = __ldg(p1 + 96);
        FMA4(a0, v0, u0); FMA4(a1, v0, u1); FMA4(a2, v0, u2); FMA4(a3, v0, u3);
        FMA4(a0, v1, w0); FMA4(a1, v1, w1); FMA4(a2, v1, w2); FMA4(a3, v1, w3);
    }
    if (i < e) {
        int   c0 = __ldg(&g_colidx[i]);
        float v0 = __ldg(&g_vals[i]);
        const float4* p0 = cur + (size_t)c0 * 128 + lane;
        float4 u0 = __ldg(p0),      u1 = __ldg(p0 + 32),
               u2 = __ldg(p0 + 64), u3 = __ldg(p0 + 96);
        FMA4(a0, v0, u0); FMA4(a1, v0, u1); FMA4(a2, v0, u2); FMA4(a3, v0, u3);
    }

    size_t o = (size_t)gw * 128 + lane;
    float4* dst = (float4*)(g_buf + (size_t)ko * N_NODES * F);
    if (first) {
        dst[o] = a0; dst[o + 32] = a1; dst[o + 64] = a2; dst[o + 96] = a3;
    } else {
        const float4* __restrict__ prev = (const float4*)(g_buf + (size_t)kp * N_NODES * F);
        float4 p0 = prev[o], p1 = prev[o + 32], p2 = prev[o + 64], p3 = prev[o + 96];
        dst[o]      = make_float4(2.f * a0.x - p0.x, 2.f * a0.y - p0.y, 2.f * a0.z - p0.z, 2.f * a0.w - p0.w);
        dst[o + 32] = make_float4(2.f * a1.x - p1.x, 2.f * a1.y - p1.y, 2.f * a1.z - p1.z, 2.f * a1.w - p1.w);
        dst[o + 64] = make_float4(2.f * a2.x - p2.x, 2.f * a2.y - p2.y, 2.f * a2.z - p2.z, 2.f * a2.w - p2.w);
        dst[o + 96] = make_float4(2.f * a3.x - p3.x, 2.f * a3.y - p3.y, 2.f * a3.z - p3.z, 2.f * a3.w - p3.w);
    }
}

// ---------------- projection v3: 2 warps/node, nk=4, W dup'd in smem, zero dup-MOVs ----------------
__device__ __forceinline__ void ffma2(ull& d, ull a, ull b) {
    asm("fma.rn.f32x2 %0, %1, %2, %0;" : "+l"(d) : "l"(a), "l"(b));
}

__global__ void __launch_bounds__(256) proj_kernel(float* __restrict__ out,
                                                   int k0, int accumulate) {
    __shared__ float swd[4 * 1024];            // 4 k-slices of dup'd W (16KB)
    int tid = threadIdx.x;
    {
        const float4* src = (const float4*)(g_Wd + k0 * 1024);
        float4* dst = (float4*)swd;
#pragma unroll
        for (int i = 0; i < 4; ++i) dst[tid + i * 256] = __ldg(src + tid + i * 256);
    }
    __syncthreads();

    int gw   = (blockIdx.x * 256 + tid) >> 5;
    int lane = tid & 31;
    int n = gw >> 1;
    int h = gw & 1;                            // bt half: [h*16, h*16+16)
    if (n >= N_NODES) return;

    int btq = lane >> 3;                       // bt quad within half
    int cj  = lane & 7;                        // couts cj*4 .. cj*4+3
    int bt0 = h * 16 + btq * 4;

    ull acc[2][4];                             // [bt pair][cout]
#pragma unroll
    for (int p = 0; p < 2; ++p)
#pragma unroll
        for (int j = 0; j < 4; ++j) acc[p][j] = 0ull;

#pragma unroll
    for (int kk = 0; kk < 4; ++kk) {
        int k = k0 + kk;
        const float* row = g_buf + ((size_t)(k & 3) * N_NODES + n) * F + bt0;
        const float* wk  = swd + kk * 1024 + cj * 8;
#pragma unroll 4
        for (int c = 0; c < C_IN; ++c) {
            float4 s4 = __ldg((const float4*)(row + c * BT));     // bts bt0..bt0+3
            float4 wA = *(const float4*)(wk + c * 64);            // couts cj*4,cj*4+1 dup'd
            float4 wB = *(const float4*)(wk + c * 64 + 4);        // couts cj*4+2,+3 dup'd
            ull s01 = ((ull*)&s4)[0], s23 = ((ull*)&s4)[1];
            ull w0 = ((ull*)&wA)[0], w1 = ((ull*)&wA)[1];
            ull w2 = ((ull*)&wB)[0], w3 = ((ull*)&wB)[1];
            ffma2(acc[0][0], s01, w0); ffma2(acc[0][1], s01, w1);
            ffma2(acc[0][2], s01, w2); ffma2(acc[0][3], s01, w3);
            ffma2(acc[1][0], s23, w0); ffma2(acc[1][1], s23, w1);
            ffma2(acc[1][2], s23, w2); ffma2(acc[1][3], s23, w3);
        }
    }

    // epilogue: acc[p][j] = { val(bt0+2p, cout j), val(bt0+2p+1, cout j) }
#pragma unroll
    for (int p = 0; p < 2; ++p) {
        float lo[4], hi[4];
#pragma unroll
        for (int j = 0; j < 4; ++j) {
            float2 v;
            asm("mov.b64 {%0, %1}, %2;" : "=f"(v.x), "=f"(v.y) : "l"(acc[p][j]));
            lo[j] = v.x; hi[j] = v.y;
        }
#pragma unroll
        for (int q = 0; q < 2; ++q) {
            int bt = bt0 + 2 * p + q;
            const float* src = q ? hi : lo;
            float* op = out + ((size_t)bt * N_NODES + n) * COUT + cj * 4;
            float4 res;
            if (accumulate) {
                float4 prev = *(const float4*)op;
                res = make_float4(prev.x + src[0], prev.y + src[1],
                                  prev.z + src[2], prev.w + src[3]);
            } else {
                res = make_float4(src[0], src[1], src[2], src[3]);
            }
            *(float4*)op = res;
        }
    }
}

// ---------------- launch ----------------
extern "C" void kernel_launch(void* const* d_in, const int* in_sizes, int n_in,
                              void* d_out, int out_size) {
    const float* x    = (const float*)d_in[0];
    const int*   erow = (const int*)  d_in[1];
    const int*   ecol = (const int*)  d_in[2];
    const float* eval = (const float*)d_in[3];
    const float* W    = (const float*)d_in[4];
    float*       out  = (float*)d_out;
    int nnz = in_sizes[1];
    if (nnz > NNZ_MAX) nnz = NNZ_MAX;

    prep_kernel       <<<1, 1024>>>(erow, W, nnz);                          // idx 0
    csr_scatter_kernel<<<(nnz + 255) / 256, 256>>>(erow, ecol, eval, nnz);  // idx 1
    sort_xpose_kernel <<<SORT_BLOCKS + XP_BLOCKS, 256>>>(x);                // idx 2

    spmm_kernel<<<WARP_BLOCKS, 256>>>(0, 0, 1, 1);                          // k=1, idx 3 <- profiled
    for (int k = 2; k < KS; ++k) {
        spmm_kernel<<<WARP_BLOCKS, 256>>>((k - 1) & 3, (k - 2) & 3, k & 3, 0);
        if ((k & 3) == 3)        // fires at k = 3, 7, 11, 15, 19 — k=19 IS the final pass
            proj_kernel<<<PROJ_BLOCKS, 256>>>(out, k - 3, k != 3);
    }
    // NOTE: no trailing proj — the k=19 in-loop launch covers slices 16..19 (R9 double-projected)
}

// round 13
// speedup vs baseline: 1.0358x; 1.0358x over previous
#include <cuda_runtime.h>
#include <stdint.h>

#define N_NODES 10242
#define NNZ_MAX 71694
#define BT      32          // B*T
#define C_IN    16
#define F       512         // C_IN * BT
#define KS      20
#define COUT    32
#define CK      (C_IN * KS)
#define NSLOT   4
#define SORT_BLOCKS 41      // 41*256 >= 10242
#define XP_BLOCKS   ((N_NODES + 7) / 8)
#define WARP_BLOCKS ((N_NODES * 32 + 255) / 256)
#define PROJ_BLOCKS ((N_NODES * 2 * 32 + 255) / 256)   // 2 warps per node

typedef unsigned long long ull;

// ---------------- device scratch (no runtime allocation allowed) ----------------
__device__ float g_buf[(size_t)NSLOT * N_NODES * F];   // rolling 4-slice window (~84MB)
__device__ int   g_rowptr[N_NODES + 1];
__device__ int   g_cursor[N_NODES];
__device__ int   g_colidx[NNZ_MAX];
__device__ float g_vals[NNZ_MAX];
__device__ float g_Wre[KS * C_IN * COUT];          // [k][c][cout] = W[cout*CK + c*KS + k]  (40KB)

// ---------------- kernel A: count+scan+W-reshape (single block) ----------------
__global__ void __launch_bounds__(1024) prep_kernel(const int* __restrict__ erow,
                                                    const float* __restrict__ W,
                                                    int nnz) {
    __shared__ int scnt[N_NODES];
    __shared__ int ssum[1024];
    int t = threadIdx.x;

    for (int i = t; i < N_NODES; i += 1024) scnt[i] = 0;
    __syncthreads();
    for (int e = t; e < nnz; e += 1024) atomicAdd(&scnt[erow[e]], 1);
    __syncthreads();

    const int CH = 11;                 // 1024*11 >= 10242
    int base = t * CH;
    int s = 0;
#pragma unroll
    for (int i = 0; i < CH; ++i) {
        int idx = base + i;
        if (idx < N_NODES) s += scnt[idx];
    }
    ssum[t] = s;
    __syncthreads();
    for (int off = 1; off < 1024; off <<= 1) {
        int v = (t >= off) ? ssum[t - off] : 0;
        __syncthreads();
        ssum[t] += v;
        __syncthreads();
    }
    int run = ssum[t] - s;
#pragma unroll
    for (int i = 0; i < CH; ++i) {
        int idx = base + i;
        if (idx < N_NODES) {
            g_rowptr[idx] = run;
            g_cursor[idx] = run;
            run += scnt[idx];
        }
    }
    if (t == 0) g_rowptr[N_NODES] = nnz;

    // W reshape: g_Wre[k*512 + c*32 + cout] = W[cout*CK + c*KS + k]
    for (int i = t; i < KS * C_IN * COUT; i += 1024) {
        int k = i >> 9;
        int r = i & 511;
        int c = r >> 5;
        int cout = r & 31;
        g_Wre[i] = W[cout * CK + c * KS + k];
    }
}

// ---------------- kernel B: scatter ----------------
__global__ void csr_scatter_kernel(const int* __restrict__ erow,
                                   const int* __restrict__ ecol,
                                   const float* __restrict__ eval, int nnz) {
    int e = blockIdx.x * blockDim.x + threadIdx.x;
    if (e < nnz) {
        int r = erow[e];
        int p = atomicAdd(&g_cursor[r], 1);
        g_colidx[p] = ecol[e];
        g_vals[p]   = eval[e];
    }
}

// ---------------- kernel C: per-row sort + transpose slice 0 (split grid) ----------------
__global__ void __launch_bounds__(256) sort_xpose_kernel(const float* __restrict__ x) {
    if (blockIdx.x < SORT_BLOCKS) {
        // canonical per-row order (col asc, then val asc) -> deterministic fp sums
        int r = blockIdx.x * 256 + threadIdx.x;
        if (r >= N_NODES) return;
        int s = g_rowptr[r], e = g_rowptr[r + 1];
        for (int i = s + 1; i < e; ++i) {
            int   kc = g_colidx[i];
            float kv = g_vals[i];
            int j = i - 1;
            while (j >= s && (g_colidx[j] > kc || (g_colidx[j] == kc && g_vals[j] > kv))) {
                g_colidx[j + 1] = g_colidx[j];
                g_vals[j + 1]   = g_vals[j];
                --j;
            }
            g_colidx[j + 1] = kc;
            g_vals[j + 1]   = kv;
        }
        return;
    }
    // transpose: x[bt=lane, n, c] -> g_buf[slot0][n, c*32+lane]
    int tid  = threadIdx.x;
    int wid  = tid >> 5;
    int lane = tid & 31;
    int n = (blockIdx.x - SORT_BLOCKS) * 8 + wid;
    if (n >= N_NODES) return;

    const float* xp = x + ((size_t)lane * N_NODES + n) * C_IN;
    float4 v0 = __ldg((const float4*)xp);
    float4 v1 = __ldg((const float4*)(xp + 4));
    float4 v2 = __ldg((const float4*)(xp + 8));
    float4 v3 = __ldg((const float4*)(xp + 12));
    float vals[16] = {v0.x, v0.y, v0.z, v0.w, v1.x, v1.y, v1.z, v1.w,
                      v2.x, v2.y, v2.z, v2.w, v3.x, v3.y, v3.z, v3.w};
    float* dst = g_buf + (size_t)n * F;
#pragma unroll
    for (int c = 0; c < C_IN; ++c) dst[c * BT + lane] = vals[c];
}

// ---------------- SpMM step (validated; rolling buffer mod 4) ----------------
#define FMA4(A, V, U) do { \
    A.x = fmaf(V, U.x, A.x); A.y = fmaf(V, U.y, A.y); \
    A.z = fmaf(V, U.z, A.z); A.w = fmaf(V, U.w, A.w); } while (0)

__global__ void __launch_bounds__(256) spmm_kernel(int kc, int kp, int ko, int first) {
    int gw   = (blockIdx.x * 256 + threadIdx.x) >> 5;   // node = global warp id
    int lane = threadIdx.x & 31;
    if (gw >= N_NODES) return;

    const float4* __restrict__ cur = (const float4*)(g_buf + (size_t)kc * N_NODES * F);
    int s = g_rowptr[gw], e = g_rowptr[gw + 1];

    float4 a0 = make_float4(0.f, 0.f, 0.f, 0.f), a1 = a0, a2 = a0, a3 = a0;

    int i = s;
    for (; i + 2 <= e; i += 2) {
        int   c0 = __ldg(&g_colidx[i]);
        int   c1 = __ldg(&g_colidx[i + 1]);
        float v0 = __ldg(&g_vals[i]);
        float v1 = __ldg(&g_vals[i + 1]);
        const float4* p0 = cur + (size_t)c0 * 128 + lane;
        const float4* p1 = cur + (size_t)c1 * 128 + lane;
        float4 u0 = __ldg(p0),      u1 = __ldg(p0 + 32),
               u2 = __ldg(p0 + 64), u3 = __ldg(p0 + 96);
        float4 w0 = __ldg(p1),      w1 = __ldg(p1 + 32),
               w2 = __ldg(p1 + 64), w3 = __ldg(p1 + 96);
        FMA4(a0, v0, u0); FMA4(a1, v0, u1); FMA4(a2, v0, u2); FMA4(a3, v0, u3);
        FMA4(a0, v1, w0); FMA4(a1, v1, w1); FMA4(a2, v1, w2); FMA4(a3, v1, w3);
    }
    if (i < e) {
        int   c0 = __ldg(&g_colidx[i]);
        float v0 = __ldg(&g_vals[i]);
        const float4* p0 = cur + (size_t)c0 * 128 + lane;
        float4 u0 = __ldg(p0),      u1 = __ldg(p0 + 32),
               u2 = __ldg(p0 + 64), u3 = __ldg(p0 + 96);
        FMA4(a0, v0, u0); FMA4(a1, v0, u1); FMA4(a2, v0, u2); FMA4(a3, v0, u3);
    }

    size_t o = (size_t)gw * 128 + lane;
    float4* dst = (float4*)(g_buf + (size_t)ko * N_NODES * F);
    if (first) {
        dst[o] = a0; dst[o + 32] = a1; dst[o + 64] = a2; dst[o + 96] = a3;
    } else {
        const float4* __restrict__ prev = (const float4*)(g_buf + (size_t)kp * N_NODES * F);
        float4 p0 = prev[o], p1 = prev[o + 32], p2 = prev[o + 64], p3 = prev[o + 96];
        dst[o]      = make_float4(2.f * a0.x - p0.x, 2.f * a0.y - p0.y, 2.f * a0.z - p0.z, 2.f * a0.w - p0.w);
        dst[o + 32] = make_float4(2.f * a1.x - p1.x, 2.f * a1.y - p1.y, 2.f * a1.z - p1.z, 2.f * a1.w - p1.w);
        dst[o + 64] = make_float4(2.f * a2.x - p2.x, 2.f * a2.y - p2.y, 2.f * a2.z - p2.z, 2.f * a2.w - p2.w);
        dst[o + 96] = make_float4(2.f * a3.x - p3.x, 2.f * a3.y - p3.y, 2.f * a3.z - p3.z, 2.f * a3.w - p3.w);
    }
}

// ---------------- projection v2.1: 2 warps/node, slices [k0, k0+nk) -> out ----------------
__device__ __forceinline__ void ffma2(ull& d, ull a, ull b) {
    asm("fma.rn.f32x2 %0, %1, %2, %0;" : "+l"(d) : "l"(a), "l"(b));
}
__device__ __forceinline__ ull dup2(float v) {
    ull r; asm("mov.b64 %0, {%1, %1};" : "=l"(r) : "f"(v)); return r;
}
__device__ __forceinline__ ull add2(ull a, ull b) {
    ull r; asm("add.rn.f32x2 %0, %1, %2;" : "=l"(r) : "l"(a), "l"(b)); return r;
}

__global__ void __launch_bounds__(256) proj_kernel(float* __restrict__ out,
                                                   int k0, int nk, int accumulate) {
    int gw   = (blockIdx.x * 256 + threadIdx.x) >> 5;   // 2 warps per node
    int lane = threadIdx.x & 31;
    int n = gw >> 1;
    int h = gw & 1;                         // bt half [h*16, h*16+16)
    if (n >= N_NODES) return;

    int btp = lane >> 3;                    // quad within half
    int cj  = lane & 7;                     // couts cj*4 .. cj*4+3
    int bt0 = h * 16 + btp * 4;             // 4 consecutive bts per thread

    ull acc[4][2];
#pragma unroll
    for (int i = 0; i < 4; ++i) { acc[i][0] = 0ull; acc[i][1] = 0ull; }

    for (int kk = 0; kk < nk; ++kk) {
        int k = k0 + kk;
        const float* row = g_buf + ((size_t)(k % NSLOT) * N_NODES + n) * F + bt0;
        const float* wk  = g_Wre + k * (C_IN * COUT) + cj * 4;
#pragma unroll 4
        for (int c = 0; c < C_IN; ++c) {
            float4 s4 = __ldg((const float4*)(row + c * BT));    // bts bt0..bt0+3
            float4 w4 = __ldg((const float4*)(wk + c * COUT));   // L1-hot
            ull w0 = ((ull*)&w4)[0], w1 = ((ull*)&w4)[1];
            ull d;
            d = dup2(s4.x); ffma2(acc[0][0], d, w0); ffma2(acc[0][1], d, w1);
            d = dup2(s4.y); ffma2(acc[1][0], d, w0); ffma2(acc[1][1], d, w1);
            d = dup2(s4.z); ffma2(acc[2][0], d, w0); ffma2(acc[2][1], d, w1);
            d = dup2(s4.w); ffma2(acc[3][0], d, w0); ffma2(acc[3][1], d, w1);
        }
    }

#pragma unroll
    for (int i = 0; i < 4; ++i) {
        int bt = bt0 + i;
        float* op = out + ((size_t)bt * N_NODES + n) * COUT + cj * 4;
        float4 res;
        if (accumulate) {
            float4 prev = *(const float4*)op;
            ((ull*)&res)[0] = add2(acc[i][0], ((ull*)&prev)[0]);
            ((ull*)&res)[1] = add2(acc[i][1], ((ull*)&prev)[1]);
        } else {
            ((ull*)&res)[0] = acc[i][0];
            ((ull*)&res)[1] = acc[i][1];
        }
        *(float4*)op = res;
    }
}

// ---------------- launch (single stream; proj every 3 steps, 7 passes) ----------------
extern "C" void kernel_launch(void* const* d_in, const int* in_sizes, int n_in,
                              void* d_out, int out_size) {
    const float* x    = (const float*)d_in[0];
    const int*   erow = (const int*)  d_in[1];
    const int*   ecol = (const int*)  d_in[2];
    const float* eval = (const float*)d_in[3];
    const float* W    = (const float*)d_in[4];
    float*       out  = (float*)d_out;
    int nnz = in_sizes[1];
    if (nnz > NNZ_MAX) nnz = NNZ_MAX;

    prep_kernel       <<<1, 1024>>>(erow, W, nnz);                          // idx 0
    csr_scatter_kernel<<<(nnz + 255) / 256, 256>>>(erow, ecol, eval, nnz);  // idx 1
    sort_xpose_kernel <<<SORT_BLOCKS + XP_BLOCKS, 256>>>(x);                // idx 2

    spmm_kernel<<<WARP_BLOCKS, 256>>>(0, 0, 1, 1);                          // k=1, idx 3 <- profiled
    for (int k = 2; k < KS; ++k) {
        spmm_kernel<<<WARP_BLOCKS, 256>>>((k - 1) % NSLOT, (k - 2) % NSLOT, k % NSLOT, 0);
        if (k % 3 == 2)   // k = 2,5,8,11,14,17 -> proj slices [k-2, k]; k=2 initializes out
            proj_kernel<<<PROJ_BLOCKS, 256>>>(out, k - 2, 3, k != 2);
    }
    proj_kernel<<<PROJ_BLOCKS, 256>>>(out, 18, 2, 1);                       // slices 18..19
}